// round 9
// baseline (speedup 1.0000x reference)
#include <cuda_runtime.h>

#define N_NODES 50000
#define N_EDGES 1600000
#define R_REL 7
#define DIM 128
#define G_GRAPHS 64
#define N_LAYERS 3
#define NR (N_NODES * R_REL)          // 350,000 segments
#define KTOT (R_REL * DIM + DIM)      // 1024

// Scratch (no cudaMalloc allowed): device globals.
__device__ float g_x[N_NODES * DIM];
__device__ float g_x2[N_NODES * DIM];
__device__ __align__(16) float g_agg[(long)NR * DIM];   // agg[n][r][d], 179 MB
__device__ __align__(16) int   g_cnt[NR];               // histogram / fill cursor
__device__ __align__(16) int   g_ptr[NR + 1];           // CSR segment pointers
__device__ int   g_bsum[128];                           // scan block sums
__device__ int2  g_epack[N_EDGES];                      // {nin, ew bits} CSR order

// ---------------------------------------------------------------------------
// x = emb[unit_type]
// ---------------------------------------------------------------------------
__global__ void gather_emb_kernel(const int* __restrict__ ut,
                                  const float* __restrict__ emb,
                                  float* __restrict__ x) {
    int t = blockIdx.x * blockDim.x + threadIdx.x;
    if (t >= N_NODES * (DIM / 4)) return;
    int n = t >> 5;
    int c = t & 31;
    float4 v = ((const float4*)(emb + (long)ut[n] * DIM))[c];
    ((float4*)(x + (long)n * DIM))[c] = v;
}

__global__ void zero_gf_kernel(float* __restrict__ out) {
    int t = blockIdx.x * blockDim.x + threadIdx.x;
    if (t < G_GRAPHS * DIM) out[t] = 0.f;
}

// ---------------------------------------------------------------------------
// CSR build keyed by seg = nout*R + rel: histogram -> 3-phase scan -> fill
// ---------------------------------------------------------------------------
__global__ void zero_cnt_kernel(int* __restrict__ cnt) {
    int t = blockIdx.x * blockDim.x + threadIdx.x;
    if (t < NR) cnt[t] = 0;
}

__global__ void count_kernel(const int* __restrict__ node_out,
                             const int* __restrict__ rel,
                             int* __restrict__ cnt) {
    int e = blockIdx.x * blockDim.x + threadIdx.x;
    if (e < N_EDGES) atomicAdd(&cnt[node_out[e] * R_REL + rel[e]], 1);
}

// Phase 1: per-block exclusive scan over 4096 elements, block totals to bsum.
__global__ __launch_bounds__(1024) void scan1_kernel(
    const int* __restrict__ cnt, int* __restrict__ excl, int* __restrict__ bsum) {
    __shared__ int wsum[32];
    int t = threadIdx.x;
    int base = blockIdx.x * 4096 + t * 4;
    int v0 = 0, v1 = 0, v2 = 0, v3 = 0;
    if (base < NR) {                       // NR % 4 == 0 -> full int4 ok
        int4 q = *(const int4*)(cnt + base);
        v0 = q.x; v1 = q.y; v2 = q.z; v3 = q.w;
    }
    int s = v0 + v1 + v2 + v3;
    int lane = t & 31, wid = t >> 5;
    int incl = s;
#pragma unroll
    for (int off = 1; off < 32; off <<= 1) {
        int u = __shfl_up_sync(0xffffffffu, incl, off);
        if (lane >= off) incl += u;
    }
    if (lane == 31) wsum[wid] = incl;
    __syncthreads();
    if (wid == 0) {
        int w = wsum[lane];
#pragma unroll
        for (int off = 1; off < 32; off <<= 1) {
            int u = __shfl_up_sync(0xffffffffu, w, off);
            if (lane >= off) w += u;
        }
        wsum[lane] = w;
    }
    __syncthreads();
    int woff = wid ? wsum[wid - 1] : 0;
    int e = woff + incl - s;               // exclusive at this thread's base
    if (base < NR)
        *(int4*)(excl + base) = make_int4(e, e + v0, e + v0 + v1, e + v0 + v1 + v2);
    if (t == 0) bsum[blockIdx.x] = wsum[31];
}

// Phase 2: serial exclusive scan of ~86 block sums (single thread, trivial).
__global__ void scan2_kernel(int* __restrict__ bsum, int nb) {
    if (threadIdx.x == 0 && blockIdx.x == 0) {
        int run = 0;
        for (int b = 0; b < nb; b++) { int v = bsum[b]; bsum[b] = run; run += v; }
    }
}

// Phase 3: add block offsets; ptr[] = exclusive prefix, cnt[] = fill cursor.
__global__ void scan3_kernel(int* __restrict__ ptr, int* __restrict__ cursor,
                             const int* __restrict__ bsum) {
    int i = blockIdx.x * blockDim.x + threadIdx.x;
    if (i < NR) {
        int v = ptr[i] + bsum[i >> 12];
        ptr[i] = v;
        cursor[i] = v;
    }
    if (i == 0) ptr[NR] = N_EDGES;
}

__global__ void fill_kernel(const int* __restrict__ node_in,
                            const int* __restrict__ node_out,
                            const int* __restrict__ rel,
                            const float* __restrict__ ew,
                            int* __restrict__ cursor,
                            int2* __restrict__ epack) {
    int e = blockIdx.x * blockDim.x + threadIdx.x;
    if (e >= N_EDGES) return;
    int seg = node_out[e] * R_REL + rel[e];
    int pos = atomicAdd(&cursor[seg], 1);
    epack[pos] = make_int2(node_in[e], __float_as_int(ew[e]));
}

// ---------------------------------------------------------------------------
// Aggregation (atomic-free): one warp per segment.
//   agg[seg, :] = sum_{e in CSR[seg]} ew_e * x[nin_e, :]
// Source x is 25.6 MB -> L2-resident; dest written once, streaming.
// ---------------------------------------------------------------------------
__global__ void gather_agg_kernel(const int* __restrict__ ptr,
                                  const int2* __restrict__ epack,
                                  const float* __restrict__ x,
                                  float* __restrict__ agg) {
    int seg = (blockIdx.x * blockDim.x + threadIdx.x) >> 5;
    if (seg >= NR) return;
    int lane = threadIdx.x & 31;
    int beg = ptr[seg], end = ptr[seg + 1];

    float4 acc = make_float4(0.f, 0.f, 0.f, 0.f);
    int i = beg;
    for (; i + 1 < end; i += 2) {
        int2 m0 = epack[i];
        int2 m1 = epack[i + 1];
        float4 v0 = ((const float4*)(x + (long)m0.x * DIM))[lane];
        float4 v1 = ((const float4*)(x + (long)m1.x * DIM))[lane];
        float w0 = __int_as_float(m0.y);
        float w1 = __int_as_float(m1.y);
        acc.x = fmaf(w0, v0.x, acc.x); acc.y = fmaf(w0, v0.y, acc.y);
        acc.z = fmaf(w0, v0.z, acc.z); acc.w = fmaf(w0, v0.w, acc.w);
        acc.x = fmaf(w1, v1.x, acc.x); acc.y = fmaf(w1, v1.y, acc.y);
        acc.z = fmaf(w1, v1.z, acc.z); acc.w = fmaf(w1, v1.w, acc.w);
    }
    if (i < end) {
        int2 m0 = epack[i];
        float4 v0 = ((const float4*)(x + (long)m0.x * DIM))[lane];
        float w0 = __int_as_float(m0.y);
        acc.x = fmaf(w0, v0.x, acc.x); acc.y = fmaf(w0, v0.y, acc.y);
        acc.z = fmaf(w0, v0.z, acc.z); acc.w = fmaf(w0, v0.w, acc.w);
    }
    ((float4*)(agg + (long)seg * DIM))[lane] = acc;
}

// ---------------------------------------------------------------------------
// Fused GEMM, K=1024:  h = relu( [agg | x] @ [W_rel ; W_loop] + br + bl )
// BM=128, BN=128, BK=8, 256 threads, 8x8 per thread via packed fma.rn.f32x2.
// ---------------------------------------------------------------------------
#define BM 128
#define BN 128
#define BK 8
#define K_REL (R_REL * DIM)   // 896

__global__ __launch_bounds__(256) void gemm_fused_kernel(
    const float* __restrict__ agg,    // (N, 896)
    const float* __restrict__ x,      // (N, 128)
    const float* __restrict__ Wrel,   // (896, 128)
    const float* __restrict__ Wloop,  // (128, 128)
    const float* __restrict__ br, const float* __restrict__ bl,
    float* __restrict__ h) {
    __shared__ float2 As2[BK][BM];    // duplicated a-values, 8 KB
    __shared__ float  Bs[BK][BN];     // 4 KB

    int tid = threadIdx.x;
    int m0  = blockIdx.x * BM;
    int trow = (tid >> 4) * 8;
    int tcol = (tid & 15) * 8;

    unsigned long long acc2[8][4];
#pragma unroll
    for (int i = 0; i < 8; i++)
#pragma unroll
        for (int j = 0; j < 4; j++) acc2[i][j] = 0ull;

    for (int k0 = 0; k0 < KTOT; k0 += BK) {
        // A tile: 128 rows x 8 k, duplicated, transposed As2[k][m]={a,a}
        {
            int ar = tid >> 1, ac = (tid & 1) * 4;
            int row = m0 + ar;
            float4 a = make_float4(0.f, 0.f, 0.f, 0.f);
            if (row < N_NODES) {
                if (k0 < K_REL)
                    a = *(const float4*)(agg + (long)row * K_REL + k0 + ac);
                else
                    a = *(const float4*)(x + (long)row * DIM + (k0 - K_REL) + ac);
            }
            As2[ac + 0][ar] = make_float2(a.x, a.x);
            As2[ac + 1][ar] = make_float2(a.y, a.y);
            As2[ac + 2][ar] = make_float2(a.z, a.z);
            As2[ac + 3][ar] = make_float2(a.w, a.w);
        }
        // B tile: 8 k x 128 cols
        {
            int brr = tid >> 5, bc = (tid & 31) * 4;
            int krow = k0 + brr;
            const float* Brow = (krow < K_REL) ? (Wrel + (long)krow * DIM)
                                               : (Wloop + (long)(krow - K_REL) * DIM);
            *(float4*)&Bs[brr][bc] = *(const float4*)(Brow + bc);
        }
        __syncthreads();
#pragma unroll
        for (int kk = 0; kk < BK; kk++) {
            unsigned long long a2[8], b2[4];
            const ulonglong2* ap = (const ulonglong2*)&As2[kk][trow];
            ulonglong2 A01 = ap[0], A23 = ap[1], A45 = ap[2], A67 = ap[3];
            a2[0] = A01.x; a2[1] = A01.y; a2[2] = A23.x; a2[3] = A23.y;
            a2[4] = A45.x; a2[5] = A45.y; a2[6] = A67.x; a2[7] = A67.y;
            const ulonglong2* bp = (const ulonglong2*)&Bs[kk][tcol];
            ulonglong2 B01 = bp[0], B23 = bp[1];
            b2[0] = B01.x; b2[1] = B01.y; b2[2] = B23.x; b2[3] = B23.y;
#pragma unroll
            for (int i = 0; i < 8; i++)
#pragma unroll
                for (int j = 0; j < 4; j++)
                    asm("fma.rn.f32x2 %0, %1, %2, %0;"
                        : "+l"(acc2[i][j]) : "l"(a2[i]), "l"(b2[j]));
        }
        __syncthreads();
    }

    float bb[8];
#pragma unroll
    for (int j = 0; j < 8; j++) bb[j] = br[tcol + j] + bl[tcol + j];

#pragma unroll
    for (int i = 0; i < 8; i++) {
        int row = m0 + trow + i;
        if (row < N_NODES) {
            float o[8];
#pragma unroll
            for (int j = 0; j < 4; j++) {
                float2 p = *(float2*)&acc2[i][j];
                o[2 * j]     = fmaxf(p.x + bb[2 * j], 0.f);
                o[2 * j + 1] = fmaxf(p.y + bb[2 * j + 1], 0.f);
            }
            *(float4*)(h + (long)row * DIM + tcol)     = *(float4*)&o[0];
            *(float4*)(h + (long)row * DIM + tcol + 4) = *(float4*)&o[4];
        }
    }
}

// ---------------------------------------------------------------------------
// Graph feature: segment-sum of final x by (sorted) node2graph.
// ---------------------------------------------------------------------------
#define NODES_PER_BLOCK 128
__global__ void graph_sum_kernel(const float* __restrict__ x,
                                 const int* __restrict__ n2g,
                                 float* __restrict__ gf) {
    int d = threadIdx.x;
    int start = blockIdx.x * NODES_PER_BLOCK;
    if (start >= N_NODES) return;
    int end = min(start + NODES_PER_BLOCK, N_NODES);
    float acc = 0.f;
    int cur = n2g[start];
    for (int nd = start; nd < end; nd++) {
        int g = n2g[nd];
        float v = x[(long)nd * DIM + d];
        if (g != cur) {
            atomicAdd(&gf[cur * DIM + d], acc);
            acc = 0.f;
            cur = g;
        }
        acc += v;
    }
    atomicAdd(&gf[cur * DIM + d], acc);
}

// ---------------------------------------------------------------------------
extern "C" void kernel_launch(void* const* d_in, const int* in_sizes, int n_in,
                              void* d_out, int out_size) {
    const int*   unit_type   = (const int*)d_in[0];
    const int*   node_in     = (const int*)d_in[1];
    const int*   node_out    = (const int*)d_in[2];
    const int*   relation    = (const int*)d_in[3];
    const float* edge_weight = (const float*)d_in[4];
    const int*   node2graph  = (const int*)d_in[5];
    const float* emb         = (const float*)d_in[6];
    const float* W_rel       = (const float*)d_in[7];
    const float* b_rel       = (const float*)d_in[8];
    const float* W_loop      = (const float*)d_in[9];
    const float* b_loop      = (const float*)d_in[10];

    float* out = (float*)d_out;
    float* gf         = out;                     // [G, D]
    float* xout_final = out + G_GRAPHS * DIM;    // [N, D]

    float *xA, *xB, *agg;
    int *cnt, *ptr, *bsum;
    int2 *epack;
    cudaGetSymbolAddress((void**)&xA,    g_x);
    cudaGetSymbolAddress((void**)&xB,    g_x2);
    cudaGetSymbolAddress((void**)&agg,   g_agg);
    cudaGetSymbolAddress((void**)&cnt,   g_cnt);
    cudaGetSymbolAddress((void**)&ptr,   g_ptr);
    cudaGetSymbolAddress((void**)&bsum,  g_bsum);
    cudaGetSymbolAddress((void**)&epack, g_epack);

    // CSR build keyed by segment (once per launch)
    const int nscan_blocks = (NR + 4095) / 4096;   // 86
    zero_cnt_kernel<<<(NR + 255) / 256, 256>>>(cnt);
    count_kernel<<<(N_EDGES + 255) / 256, 256>>>(node_out, relation, cnt);
    scan1_kernel<<<nscan_blocks, 1024>>>(cnt, ptr, bsum);
    scan2_kernel<<<1, 32>>>(bsum, nscan_blocks);
    scan3_kernel<<<(NR + 255) / 256, 256>>>(ptr, cnt, bsum);
    fill_kernel<<<(N_EDGES + 255) / 256, 256>>>(node_in, node_out, relation,
                                                edge_weight, cnt, epack);

    gather_emb_kernel<<<(N_NODES * (DIM / 4) + 255) / 256, 256>>>(unit_type, emb, xA);
    zero_gf_kernel<<<(G_GRAPHS * DIM + 255) / 256, 256>>>(gf);

    const int gemm_grid = (N_NODES + BM - 1) / BM;          // 391
    const int agg_grid  = ((long)NR * 32 + 255) / 256;      // 43750

    const float* xin = xA;
    for (int l = 0; l < N_LAYERS; l++) {
        float* h = (l == N_LAYERS - 1) ? xout_final
                                       : ((xin == xA) ? xB : xA);
        gather_agg_kernel<<<agg_grid, 256>>>(ptr, epack, xin, agg);
        gemm_fused_kernel<<<gemm_grid, 256>>>(
            agg, xin,
            W_rel  + (long)l * K_REL * DIM,
            W_loop + (long)l * DIM * DIM,
            b_rel  + (long)l * DIM,
            b_loop + (long)l * DIM,
            h);
        xin = h;
    }

    graph_sum_kernel<<<(N_NODES + NODES_PER_BLOCK - 1) / NODES_PER_BLOCK,
                       NODES_PER_BLOCK>>>(xout_final, node2graph, gf);
}